// round 5
// baseline (speedup 1.0000x reference)
#include <cuda_runtime.h>
#include <math.h>
#include <stdint.h>

#define BB 32
#define TT 4096
#define DD 512
#define UU 256

#define AP 36     // As pitch (floats)
#define BP 264    // Bs pitch (floats)

// scratch (no allocations allowed)
__device__ float g_hq[BB * UU];
__device__ float g_scores[BB * TT];
__device__ float g_W1r[DD * UU];    // W1, tf32(rna)-rounded, [k][u]

__device__ __forceinline__ float f2tf32f(float f) {
    uint32_t r;
    asm("cvt.rna.tf32.f32 %0, %1;" : "=r"(r) : "f"(f));
    return __uint_as_float(r);
}
__device__ __forceinline__ uint32_t smem_u32(const void* p) {
    uint32_t a;
    asm("{ .reg .u64 t; cvta.to.shared.u64 t, %1; cvt.u32.u64 %0, t; }"
        : "=r"(a) : "l"(p));
    return a;
}
__device__ __forceinline__ void cp_async16(uint32_t dst, const void* src) {
    asm volatile("cp.async.cg.shared.global [%0], [%1], 16;"
                 :: "r"(dst), "l"(src) : "memory");
}
__device__ __forceinline__ void cp_commit() {
    asm volatile("cp.async.commit_group;" ::: "memory");
}
__device__ __forceinline__ void cp_wait0() {
    asm volatile("cp.async.wait_group 0;" ::: "memory");
}
__device__ __forceinline__ void mma_tf32(float c[4], const uint32_t a[4],
                                         const uint32_t b[2]) {
    asm volatile(
        "mma.sync.aligned.m16n8k8.row.col.f32.tf32.tf32.f32 "
        "{%0,%1,%2,%3}, {%4,%5,%6,%7}, {%8,%9}, {%0,%1,%2,%3};"
        : "+f"(c[0]), "+f"(c[1]), "+f"(c[2]), "+f"(c[3])
        : "r"(a[0]), "r"(a[1]), "r"(a[2]), "r"(a[3]), "r"(b[0]), "r"(b[1]));
}

// ---------------------------------------------------------------------------
__global__ void w1r_kernel(const float* __restrict__ W1) {
    const int i = blockIdx.x * 256 + threadIdx.x;
    g_W1r[i] = f2tf32f(W1[i]);
}

// ---------------------------------------------------------------------------
__global__ void hq_kernel(const float* __restrict__ query,
                          const float* __restrict__ W2,
                          const float* __restrict__ b1,
                          const float* __restrict__ b2) {
    __shared__ float q[DD];
    const int b = blockIdx.x;
    const int u = threadIdx.x;
    for (int i = threadIdx.x; i < DD; i += blockDim.x) q[i] = query[b * DD + i];
    __syncthreads();
    float acc = b1[u] + b2[u];
#pragma unroll 8
    for (int d = 0; d < DD; ++d) acc = fmaf(q[d], W2[d * UU + u], acc);
    g_hq[b * UU + u] = acc;
}

// ---------------------------------------------------------------------------
// scores: tf32 mma, CTA = 64t x 256u x 512k, 256 threads (8 warps, 2M x 4N),
// 2 CTAs/SM for barrier/latency overlap. Double-buffered staging:
// cp.async for W1r, register-prefetch+cvt for values.
// grid (TT/64, BB), block 256
// ---------------------------------------------------------------------------
__global__ __launch_bounds__(256, 2)
void scores_mma(const float* __restrict__ values,
                const float* __restrict__ Vv) {
    extern __shared__ float sm[];
    float* As   = sm;                     // 2 x [64][AP]
    float* Bs   = sm + 2 * 64 * AP;       // 2 x [32][BP]
    float* sred = Bs + 2 * 32 * BP;       // [64]
    const uint32_t Bs_u32 = smem_u32(Bs);

    const int b     = blockIdx.y;
    const int tbase = blockIdx.x * 64;
    const int tid   = threadIdx.x;
    const int lane  = tid & 31;
    const int wid   = tid >> 5;
    const int wm    = wid & 1;            // M half: 2 x 32 t
    const int wn    = wid >> 1;           // N: 4 x 64 u
    const int g     = lane >> 2;
    const int tg    = lane & 3;

    const float* vbase = values + ((size_t)b * TT + tbase) * DD;

    // staging coordinates
    const int at0 = tid >> 3;             // A rows 0..31 -> rows at0, at0+32
    const int k4a = tid & 7;
    const int bk  = tid >> 4;             // B row k (0..15) -> bk, bk+16
    const int bu  = (tid & 15) * 16;      // 16 floats = 4 x 16B

    float acc[2][8][4];
#pragma unroll
    for (int i = 0; i < 2; ++i)
#pragma unroll
        for (int j = 0; j < 8; ++j)
#pragma unroll
            for (int c = 0; c < 4; ++c) acc[i][j][c] = 0.f;

    float4 pfA0, pfA1;

    // ---- prologue: stage chunk 0 ----
    {
        const float* w1p = g_W1r + (size_t)bk * UU + bu;
        uint32_t bdst = Bs_u32 + (bk * BP + bu) * 4;
#pragma unroll
        for (int x = 0; x < 4; ++x) cp_async16(bdst + x * 16, w1p + x * 4);
        const float* w1p2 = g_W1r + (size_t)(bk + 16) * UU + bu;
        uint32_t bdst2 = Bs_u32 + ((bk + 16) * BP + bu) * 4;
#pragma unroll
        for (int x = 0; x < 4; ++x) cp_async16(bdst2 + x * 16, w1p2 + x * 4);
        cp_commit();
        pfA0 = *(const float4*)(vbase + (size_t)at0 * DD + k4a * 4);
        pfA1 = *(const float4*)(vbase + (size_t)(at0 + 32) * DD + k4a * 4);
        float4 o0, o1;
        o0.x = f2tf32f(pfA0.x); o0.y = f2tf32f(pfA0.y);
        o0.z = f2tf32f(pfA0.z); o0.w = f2tf32f(pfA0.w);
        o1.x = f2tf32f(pfA1.x); o1.y = f2tf32f(pfA1.y);
        o1.z = f2tf32f(pfA1.z); o1.w = f2tf32f(pfA1.w);
        *(float4*)&As[at0 * AP + k4a * 4] = o0;
        *(float4*)&As[(at0 + 32) * AP + k4a * 4] = o1;
        cp_wait0();
    }
    __syncthreads();

    for (int c = 0; c < 16; ++c) {
        const int buf = c & 1;
        const int nxt = buf ^ 1;

        if (c < 15) {
            const int k0n = (c + 1) * 32;
            const float* w1p = g_W1r + (size_t)(k0n + bk) * UU + bu;
            uint32_t bdst = Bs_u32 + (nxt * 32 * BP + bk * BP + bu) * 4;
#pragma unroll
            for (int x = 0; x < 4; ++x) cp_async16(bdst + x * 16, w1p + x * 4);
            const float* w1p2 = g_W1r + (size_t)(k0n + bk + 16) * UU + bu;
            uint32_t bdst2 = Bs_u32 + (nxt * 32 * BP + (bk + 16) * BP + bu) * 4;
#pragma unroll
            for (int x = 0; x < 4; ++x) cp_async16(bdst2 + x * 16, w1p2 + x * 4);
            cp_commit();
            pfA0 = *(const float4*)(vbase + (size_t)at0 * DD + k0n + k4a * 4);
            pfA1 = *(const float4*)(vbase + (size_t)(at0 + 32) * DD + k0n + k4a * 4);
        }

        // ---- compute chunk c ----
        const float* Ab = As + buf * 64 * AP;
        const float* Bb = Bs + buf * 32 * BP;
#pragma unroll
        for (int ks = 0; ks < 4; ++ks) {
            const int kk = ks * 8;
            uint32_t a[2][4];
#pragma unroll
            for (int mi = 0; mi < 2; ++mi) {
                const int row = wm * 32 + mi * 16 + g;
                a[mi][0] = __float_as_uint(Ab[row * AP + kk + tg]);
                a[mi][1] = __float_as_uint(Ab[(row + 8) * AP + kk + tg]);
                a[mi][2] = __float_as_uint(Ab[row * AP + kk + 4 + tg]);
                a[mi][3] = __float_as_uint(Ab[(row + 8) * AP + kk + 4 + tg]);
            }
            uint32_t bf[8][2];
#pragma unroll
            for (int nj = 0; nj < 8; ++nj) {
                const int u = wn * 64 + nj * 8 + g;
                bf[nj][0] = __float_as_uint(Bb[(kk + tg) * BP + u]);
                bf[nj][1] = __float_as_uint(Bb[(kk + 4 + tg) * BP + u]);
            }
#pragma unroll
            for (int mi = 0; mi < 2; ++mi)
#pragma unroll
                for (int nj = 0; nj < 8; ++nj)
                    mma_tf32(acc[mi][nj], a[mi], bf[nj]);
        }

        if (c < 15) {
            float* An = As + nxt * 64 * AP;
            float4 o0, o1;
            o0.x = f2tf32f(pfA0.x); o0.y = f2tf32f(pfA0.y);
            o0.z = f2tf32f(pfA0.z); o0.w = f2tf32f(pfA0.w);
            o1.x = f2tf32f(pfA1.x); o1.y = f2tf32f(pfA1.y);
            o1.z = f2tf32f(pfA1.z); o1.w = f2tf32f(pfA1.w);
            *(float4*)&An[at0 * AP + k4a * 4] = o0;
            *(float4*)&An[(at0 + 32) * AP + k4a * 4] = o1;
            cp_wait0();
            __syncthreads();
        }
    }

    // ---- epilogue: tanh + dot with V, reduce over u ----
    float sp[2][2];
    sp[0][0] = sp[0][1] = sp[1][0] = sp[1][1] = 0.f;

#pragma unroll
    for (int nj = 0; nj < 8; ++nj) {
        const int u0  = wn * 64 + nj * 8 + 2 * tg;
        const float h0 = g_hq[b * UU + u0];
        const float h1 = g_hq[b * UU + u0 + 1];
        const float v0 = Vv[u0];
        const float v1 = Vv[u0 + 1];
#pragma unroll
        for (int mi = 0; mi < 2; ++mi) {
            sp[mi][0] = fmaf(tanhf(acc[mi][nj][0] + h0), v0, sp[mi][0]);
            sp[mi][0] = fmaf(tanhf(acc[mi][nj][1] + h1), v1, sp[mi][0]);
            sp[mi][1] = fmaf(tanhf(acc[mi][nj][2] + h0), v0, sp[mi][1]);
            sp[mi][1] = fmaf(tanhf(acc[mi][nj][3] + h1), v1, sp[mi][1]);
        }
    }
#pragma unroll
    for (int off = 1; off <= 2; off <<= 1)
#pragma unroll
        for (int mi = 0; mi < 2; ++mi) {
            sp[mi][0] += __shfl_xor_sync(0xffffffffu, sp[mi][0], off);
            sp[mi][1] += __shfl_xor_sync(0xffffffffu, sp[mi][1], off);
        }

    if (tid < 64) sred[tid] = 0.f;
    __syncthreads();
    if (tg == 0) {
#pragma unroll
        for (int mi = 0; mi < 2; ++mi) {
            atomicAdd(&sred[wm * 32 + mi * 16 + g],     sp[mi][0]);
            atomicAdd(&sred[wm * 32 + mi * 16 + g + 8], sp[mi][1]);
        }
    }
    __syncthreads();
    if (tid < 64) g_scores[(size_t)b * TT + tbase + tid] = sred[tid];
}

// ---------------------------------------------------------------------------
// softmax over T per batch; 1024 threads
// ---------------------------------------------------------------------------
__global__ void softmax_kernel(float* __restrict__ wout) {
    __shared__ float red[32];
    __shared__ float bcast;
    const int b   = blockIdx.x;
    const int tid = threadIdx.x;
    float* s = g_scores + (size_t)b * TT;

    float m = -3.4e38f;
    for (int i = tid; i < TT; i += 1024) m = fmaxf(m, s[i]);
#pragma unroll
    for (int off = 16; off; off >>= 1)
        m = fmaxf(m, __shfl_xor_sync(0xffffffffu, m, off));
    if ((tid & 31) == 0) red[tid >> 5] = m;
    __syncthreads();
    if (tid == 0) {
        float mm = red[0];
        for (int i = 1; i < 32; ++i) mm = fmaxf(mm, red[i]);
        bcast = mm;
    }
    __syncthreads();
    m = bcast;

    float sum = 0.f;
    for (int i = tid; i < TT; i += 1024) {
        const float e = expf(s[i] - m);
        s[i] = e;
        sum += e;
    }
#pragma unroll
    for (int off = 16; off; off >>= 1)
        sum += __shfl_xor_sync(0xffffffffu, sum, off);
    if ((tid & 31) == 0) red[tid >> 5] = sum;
    __syncthreads();
    if (tid == 0) {
        float t = 0.f;
        for (int i = 0; i < 32; ++i) t += red[i];
        bcast = 1.f / t;
    }
    __syncthreads();
    const float inv = bcast;

    for (int i = tid; i < TT; i += 1024) {
        const float wv = s[i] * inv;
        s[i] = wv;
        if (wout) wout[(size_t)b * TT + i] = wv;
    }
}

// ---------------------------------------------------------------------------
// context[b][d] = sum_t weights[b][t] * values[b][t][d]
// ---------------------------------------------------------------------------
__global__ void zero_ctx_kernel(float* __restrict__ ctx) {
    ctx[blockIdx.x * 256 + threadIdx.x] = 0.f;
}

__global__ void ctx_kernel(const float* __restrict__ values,
                           float* __restrict__ ctx) {
    const int b  = blockIdx.y;
    const int d4 = threadIdx.x;                // 0..127
    const int tstart = blockIdx.x * (TT / 32);
    const float4* vb = (const float4*)(values + (size_t)b * TT * DD) + d4;
    const float*  w  = g_scores + (size_t)b * TT;

    float4 acc = make_float4(0.f, 0.f, 0.f, 0.f);
#pragma unroll 4
    for (int t = tstart; t < tstart + TT / 32; ++t) {
        const float wv = w[t];
        const float4 v = vb[(size_t)t * (DD / 4)];
        acc.x = fmaf(wv, v.x, acc.x);
        acc.y = fmaf(wv, v.y, acc.y);
        acc.z = fmaf(wv, v.z, acc.z);
        acc.w = fmaf(wv, v.w, acc.w);
    }
    float* o = ctx + b * DD + d4 * 4;
    atomicAdd(o + 0, acc.x);
    atomicAdd(o + 1, acc.y);
    atomicAdd(o + 2, acc.z);
    atomicAdd(o + 3, acc.w);
}

// ---------------------------------------------------------------------------
extern "C" void kernel_launch(void* const* d_in, const int* in_sizes, int n_in,
                              void* d_out, int out_size) {
    const float* values = (const float*)d_in[0];
    const float* query  = (const float*)d_in[1];
    const float* W1     = (const float*)d_in[2];
    const float* b1     = (const float*)d_in[3];
    const float* W2     = (const float*)d_in[4];
    const float* b2     = (const float*)d_in[5];
    const float* Vv     = (const float*)d_in[6];
    // d_in[7] = bV: constant logit shift, cancels exactly in softmax.

    float* out  = (float*)d_out;
    float* ctx  = nullptr;
    float* wout = nullptr;
    if (out_size >= BB * DD + BB * TT) {
        ctx  = out;
        wout = out + BB * DD;
    } else if (out_size == BB * TT) {
        wout = out;
    } else {
        ctx = out;
    }

    const int smem_bytes = (2 * 64 * AP + 2 * 32 * BP + 64) * sizeof(float);
    cudaFuncSetAttribute(scores_mma, cudaFuncAttributeMaxDynamicSharedMemorySize,
                         smem_bytes);

    w1r_kernel<<<(DD * UU) / 256, 256>>>(W1);
    hq_kernel<<<BB, 256>>>(query, W2, b1, b2);
    scores_mma<<<dim3(TT / 64, BB), 256, smem_bytes>>>(values, Vv);
    softmax_kernel<<<BB, 1024>>>(wout);
    if (ctx) {
        zero_ctx_kernel<<<(BB * DD) / 256, 256>>>(ctx);
        ctx_kernel<<<dim3(32, BB), 128>>>(values, ctx);
    }
}

// round 6
// speedup vs baseline: 1.6581x; 1.6581x over previous
#include <cuda_runtime.h>
#include <cuda_fp16.h>
#include <math.h>
#include <stdint.h>

#define BB 32
#define TT 4096
#define DD 512
#define UU 256

#define APH 40    // As pitch in halves (32 k + 8 pad)
#define BPH 40    // Bs pitch in halves

// scratch (no allocations allowed)
__device__ float  g_hq[BB * UU];
__device__ float  g_scores[BB * TT];
__device__ __half g_W1h[UU * DD];   // W1 transposed [u][k], fp16

__device__ __forceinline__ uint32_t smem_u32(const void* p) {
    uint32_t a;
    asm("{ .reg .u64 t; cvta.to.shared.u64 t, %1; cvt.u32.u64 %0, t; }"
        : "=r"(a) : "l"(p));
    return a;
}
__device__ __forceinline__ void cp_async16(uint32_t dst, const void* src) {
    asm volatile("cp.async.cg.shared.global [%0], [%1], 16;"
                 :: "r"(dst), "l"(src) : "memory");
}
__device__ __forceinline__ void cp_commit() {
    asm volatile("cp.async.commit_group;" ::: "memory");
}
__device__ __forceinline__ void cp_wait0() {
    asm volatile("cp.async.wait_group 0;" ::: "memory");
}
__device__ __forceinline__ void mma_f16(float c[4], const uint32_t a[4],
                                        const uint32_t b[2]) {
    asm volatile(
        "mma.sync.aligned.m16n8k16.row.col.f32.f16.f16.f32 "
        "{%0,%1,%2,%3}, {%4,%5,%6,%7}, {%8,%9}, {%0,%1,%2,%3};"
        : "+f"(c[0]), "+f"(c[1]), "+f"(c[2]), "+f"(c[3])
        : "r"(a[0]), "r"(a[1]), "r"(a[2]), "r"(a[3]), "r"(b[0]), "r"(b[1]));
}

// ---------------------------------------------------------------------------
// g_W1h[u][k] = half(W1[k][u])  — 32x32 smem tile transpose + convert
// ---------------------------------------------------------------------------
__global__ void w1h_kernel(const float* __restrict__ W1) {
    __shared__ float sm[32][33];
    const int k0 = blockIdx.x * 32, u0 = blockIdx.y * 32;
    const int tx = threadIdx.x, ty = threadIdx.y;
#pragma unroll
    for (int j = 0; j < 4; ++j) {
        const int r = ty + j * 8;
        sm[r][tx] = W1[(size_t)(k0 + r) * UU + u0 + tx];
    }
    __syncthreads();
#pragma unroll
    for (int j = 0; j < 4; ++j) {
        const int r = ty + j * 8;
        g_W1h[(size_t)(u0 + r) * DD + k0 + tx] = __float2half_rn(sm[tx][r]);
    }
}

// ---------------------------------------------------------------------------
// hq[b][u] = query[b,:] @ W2[:,u] + b2[u] + b1[u]
// ---------------------------------------------------------------------------
__global__ void hq_kernel(const float* __restrict__ query,
                          const float* __restrict__ W2,
                          const float* __restrict__ b1,
                          const float* __restrict__ b2) {
    __shared__ float q[DD];
    const int b = blockIdx.x;
    const int u = threadIdx.x;
    for (int i = threadIdx.x; i < DD; i += blockDim.x) q[i] = query[b * DD + i];
    __syncthreads();
    float acc = b1[u] + b2[u];
#pragma unroll 8
    for (int d = 0; d < DD; ++d) acc = fmaf(q[d], W2[d * UU + u], acc);
    g_hq[b * UU + u] = acc;
}

// ---------------------------------------------------------------------------
// scores: fp16 mma.m16n8k16 (f32 accum), CTA = 128t x 256u x 512k,
// 512 threads (16 warps, 2M x 8N -> 64x32 per warp), K-chunks of 32,
// double-buffered: cp.async for W1h ([u][k] halves), reg-prefetch+cvt for A.
// grid (TT/128, BB)
// ---------------------------------------------------------------------------
__global__ __launch_bounds__(512, 1)
void scores_mma(const float* __restrict__ values,
                const float* __restrict__ Vv) {
    extern __shared__ char smc[];
    __half* As   = (__half*)smc;                 // 2 x [128][APH]
    __half* Bs   = (__half*)(smc + 20480);       // 2 x [256][BPH]
    float*  sred = (float*)(smc + 61440);        // [128]
    const uint32_t Bs_u32 = smem_u32(Bs);

    const int b     = blockIdx.y;
    const int tbase = blockIdx.x * 128;
    const int tid   = threadIdx.x;
    const int lane  = tid & 31;
    const int wid   = tid >> 5;
    const int wm    = wid & 1;            // M half (64 rows each)
    const int wn    = wid >> 1;           // N: 8 x 32 u
    const int g     = lane >> 2;
    const int tg    = lane & 3;

    const float* vbase = values + ((size_t)b * TT + tbase) * DD;

    // staging coords
    const int at0 = tid >> 3;             // A rows at0, at0+64 ; col k4a*4 floats
    const int k4a = tid & 7;
    const int ub  = tid >> 1;             // B row u (0..255)
    const int hk  = (tid & 1) * 16;       // halves offset within 32-k row

    float acc[4][4][4];
#pragma unroll
    for (int i = 0; i < 4; ++i)
#pragma unroll
        for (int j = 0; j < 4; ++j)
#pragma unroll
            for (int c = 0; c < 4; ++c) acc[i][j][c] = 0.f;

    float4 pfA0, pfA1;

    // ---- prologue: stage chunk 0 ----
    {
        const __half* w1p = g_W1h + (size_t)ub * DD + hk;
        const uint32_t bdst = Bs_u32 + (ub * BPH + hk) * 2;
        cp_async16(bdst, w1p);
        cp_async16(bdst + 16, w1p + 8);
        cp_commit();
        pfA0 = *(const float4*)(vbase + (size_t)at0 * DD + k4a * 4);
        pfA1 = *(const float4*)(vbase + (size_t)(at0 + 64) * DD + k4a * 4);
        __half2 p0 = __floats2half2_rn(pfA0.x, pfA0.y);
        __half2 p1 = __floats2half2_rn(pfA0.z, pfA0.w);
        __half2 p2 = __floats2half2_rn(pfA1.x, pfA1.y);
        __half2 p3 = __floats2half2_rn(pfA1.z, pfA1.w);
        uint2 s0 = make_uint2(*(uint32_t*)&p0, *(uint32_t*)&p1);
        uint2 s1 = make_uint2(*(uint32_t*)&p2, *(uint32_t*)&p3);
        *(uint2*)(As + at0 * APH + k4a * 4) = s0;
        *(uint2*)(As + (at0 + 64) * APH + k4a * 4) = s1;
        cp_wait0();
    }
    __syncthreads();

    for (int c = 0; c < 16; ++c) {
        const int buf = c & 1;
        const int nxt = buf ^ 1;

        if (c < 15) {
            const int k0n = (c + 1) * 32;
            const __half* w1p = g_W1h + (size_t)ub * DD + k0n + hk;
            const uint32_t bdst = Bs_u32 + (nxt * 256 * BPH + ub * BPH + hk) * 2;
            cp_async16(bdst, w1p);
            cp_async16(bdst + 16, w1p + 8);
            cp_commit();
            pfA0 = *(const float4*)(vbase + (size_t)at0 * DD + k0n + k4a * 4);
            pfA1 = *(const float4*)(vbase + (size_t)(at0 + 64) * DD + k0n + k4a * 4);
        }

        // ---- compute chunk c (2 k16 steps) ----
        const __half* Ab = As + buf * 128 * APH;
        const __half* Bb = Bs + buf * 256 * BPH;
#pragma unroll
        for (int ks = 0; ks < 2; ++ks) {
            const int kk = ks * 16;
            uint32_t a[4][4];
#pragma unroll
            for (int mi = 0; mi < 4; ++mi) {
                const int row = wm * 64 + mi * 16 + g;
                a[mi][0] = *(const uint32_t*)(Ab + row * APH + kk + 2 * tg);
                a[mi][1] = *(const uint32_t*)(Ab + (row + 8) * APH + kk + 2 * tg);
                a[mi][2] = *(const uint32_t*)(Ab + row * APH + kk + 8 + 2 * tg);
                a[mi][3] = *(const uint32_t*)(Ab + (row + 8) * APH + kk + 8 + 2 * tg);
            }
            uint32_t bf[4][2];
#pragma unroll
            for (int nj = 0; nj < 4; ++nj) {
                const int u = wn * 32 + nj * 8 + g;
                bf[nj][0] = *(const uint32_t*)(Bb + u * BPH + kk + 2 * tg);
                bf[nj][1] = *(const uint32_t*)(Bb + u * BPH + kk + 8 + 2 * tg);
            }
#pragma unroll
            for (int mi = 0; mi < 4; ++mi)
#pragma unroll
                for (int nj = 0; nj < 4; ++nj)
                    mma_f16(acc[mi][nj], a[mi], bf[nj]);
        }

        if (c < 15) {
            __half* An = As + nxt * 128 * APH;
            __half2 p0 = __floats2half2_rn(pfA0.x, pfA0.y);
            __half2 p1 = __floats2half2_rn(pfA0.z, pfA0.w);
            __half2 p2 = __floats2half2_rn(pfA1.x, pfA1.y);
            __half2 p3 = __floats2half2_rn(pfA1.z, pfA1.w);
            uint2 s0 = make_uint2(*(uint32_t*)&p0, *(uint32_t*)&p1);
            uint2 s1 = make_uint2(*(uint32_t*)&p2, *(uint32_t*)&p3);
            *(uint2*)(An + at0 * APH + k4a * 4) = s0;
            *(uint2*)(An + (at0 + 64) * APH + k4a * 4) = s1;
            cp_wait0();
            __syncthreads();
        }
    }

    // ---- epilogue: tanh + dot with V, reduce over u ----
    float sp[4][2];
#pragma unroll
    for (int mi = 0; mi < 4; ++mi) { sp[mi][0] = 0.f; sp[mi][1] = 0.f; }

#pragma unroll
    for (int nj = 0; nj < 4; ++nj) {
        const int u0  = wn * 32 + nj * 8 + 2 * tg;
        const float h0 = g_hq[b * UU + u0];
        const float h1 = g_hq[b * UU + u0 + 1];
        const float v0 = Vv[u0];
        const float v1 = Vv[u0 + 1];
#pragma unroll
        for (int mi = 0; mi < 4; ++mi) {
            sp[mi][0] = fmaf(tanhf(acc[mi][nj][0] + h0), v0, sp[mi][0]);
            sp[mi][0] = fmaf(tanhf(acc[mi][nj][1] + h1), v1, sp[mi][0]);
            sp[mi][1] = fmaf(tanhf(acc[mi][nj][2] + h0), v0, sp[mi][1]);
            sp[mi][1] = fmaf(tanhf(acc[mi][nj][3] + h1), v1, sp[mi][1]);
        }
    }
#pragma unroll
    for (int off = 1; off <= 2; off <<= 1)
#pragma unroll
        for (int mi = 0; mi < 4; ++mi) {
            sp[mi][0] += __shfl_xor_sync(0xffffffffu, sp[mi][0], off);
            sp[mi][1] += __shfl_xor_sync(0xffffffffu, sp[mi][1], off);
        }

    if (tid < 128) sred[tid] = 0.f;
    __syncthreads();
    if (tg == 0) {
#pragma unroll
        for (int mi = 0; mi < 4; ++mi) {
            atomicAdd(&sred[wm * 64 + mi * 16 + g],     sp[mi][0]);
            atomicAdd(&sred[wm * 64 + mi * 16 + g + 8], sp[mi][1]);
        }
    }
    __syncthreads();
    if (tid < 128) g_scores[(size_t)b * TT + tbase + tid] = sred[tid];
}

// ---------------------------------------------------------------------------
// softmax over T per batch; 1024 threads
// ---------------------------------------------------------------------------
__global__ void softmax_kernel(float* __restrict__ wout) {
    __shared__ float red[32];
    __shared__ float bcast;
    const int b   = blockIdx.x;
    const int tid = threadIdx.x;
    float* s = g_scores + (size_t)b * TT;

    float m = -3.4e38f;
    for (int i = tid; i < TT; i += 1024) m = fmaxf(m, s[i]);
#pragma unroll
    for (int off = 16; off; off >>= 1)
        m = fmaxf(m, __shfl_xor_sync(0xffffffffu, m, off));
    if ((tid & 31) == 0) red[tid >> 5] = m;
    __syncthreads();
    if (tid == 0) {
        float mm = red[0];
        for (int i = 1; i < 32; ++i) mm = fmaxf(mm, red[i]);
        bcast = mm;
    }
    __syncthreads();
    m = bcast;

    float sum = 0.f;
    for (int i = tid; i < TT; i += 1024) {
        const float e = expf(s[i] - m);
        s[i] = e;
        sum += e;
    }
#pragma unroll
    for (int off = 16; off; off >>= 1)
        sum += __shfl_xor_sync(0xffffffffu, sum, off);
    if ((tid & 31) == 0) red[tid >> 5] = sum;
    __syncthreads();
    if (tid == 0) {
        float t = 0.f;
        for (int i = 0; i < 32; ++i) t += red[i];
        bcast = 1.f / t;
    }
    __syncthreads();
    const float inv = bcast;

    for (int i = tid; i < TT; i += 1024) {
        const float wv = s[i] * inv;
        s[i] = wv;
        if (wout) wout[(size_t)b * TT + i] = wv;
    }
}

// ---------------------------------------------------------------------------
// context[b][d] = sum_t weights[b][t] * values[b][t][d]
// ---------------------------------------------------------------------------
__global__ void zero_ctx_kernel(float* __restrict__ ctx) {
    ctx[blockIdx.x * 256 + threadIdx.x] = 0.f;
}

__global__ void ctx_kernel(const float* __restrict__ values,
                           float* __restrict__ ctx) {
    const int b  = blockIdx.y;
    const int d4 = threadIdx.x;                // 0..127
    const int tstart = blockIdx.x * (TT / 32);
    const float4* vb = (const float4*)(values + (size_t)b * TT * DD) + d4;
    const float*  w  = g_scores + (size_t)b * TT;

    float4 acc = make_float4(0.f, 0.f, 0.f, 0.f);
#pragma unroll 4
    for (int t = tstart; t < tstart + TT / 32; ++t) {
        const float wv = w[t];
        const float4 v = vb[(size_t)t * (DD / 4)];
        acc.x = fmaf(wv, v.x, acc.x);
        acc.y = fmaf(wv, v.y, acc.y);
        acc.z = fmaf(wv, v.z, acc.z);
        acc.w = fmaf(wv, v.w, acc.w);
    }
    float* o = ctx + b * DD + d4 * 4;
    atomicAdd(o + 0, acc.x);
    atomicAdd(o + 1, acc.y);
    atomicAdd(o + 2, acc.z);
    atomicAdd(o + 3, acc.w);
}

// ---------------------------------------------------------------------------
extern "C" void kernel_launch(void* const* d_in, const int* in_sizes, int n_in,
                              void* d_out, int out_size) {
    const float* values = (const float*)d_in[0];
    const float* query  = (const float*)d_in[1];
    const float* W1     = (const float*)d_in[2];
    const float* b1     = (const float*)d_in[3];
    const float* W2     = (const float*)d_in[4];
    const float* b2     = (const float*)d_in[5];
    const float* Vv     = (const float*)d_in[6];
    // d_in[7] = bV: constant logit shift, cancels exactly in softmax.

    float* out  = (float*)d_out;
    float* ctx  = nullptr;
    float* wout = nullptr;
    if (out_size >= BB * DD + BB * TT) {
        ctx  = out;
        wout = out + BB * DD;
    } else if (out_size == BB * TT) {
        wout = out;
    } else {
        ctx = out;
    }

    const int smem_bytes = 61440 + 128 * sizeof(float);
    cudaFuncSetAttribute(scores_mma, cudaFuncAttributeMaxDynamicSharedMemorySize,
                         smem_bytes);

    w1h_kernel<<<dim3(DD / 32, UU / 32), dim3(32, 8)>>>(W1);
    hq_kernel<<<BB, 256>>>(query, W2, b1, b2);
    scores_mma<<<dim3(TT / 128, BB), 512, smem_bytes>>>(values, Vv);
    softmax_kernel<<<BB, 1024>>>(wout);
    if (ctx) {
        zero_ctx_kernel<<<(BB * DD) / 256, 256>>>(ctx);
        ctx_kernel<<<dim3(32, BB), 128>>>(values, ctx);
    }
}

// round 7
// speedup vs baseline: 1.7410x; 1.0500x over previous
#include <cuda_runtime.h>
#include <cuda_fp16.h>
#include <math.h>
#include <stdint.h>

#define BB 32
#define TT 4096
#define DD 512
#define UU 256

#define APH 40    // As pitch in halves (32 k + 8 pad) -> 80B rows, LDSM-conflict-free
#define BPH 40    // Bs pitch in halves

// scratch (no allocations allowed)
__device__ float  g_hq[BB * UU];
__device__ float  g_scores[BB * TT];
__device__ __half g_W1h[UU * DD];   // W1 transposed [u][k], fp16

__device__ __forceinline__ uint32_t smem_u32(const void* p) {
    uint32_t a;
    asm("{ .reg .u64 t; cvta.to.shared.u64 t, %1; cvt.u32.u64 %0, t; }"
        : "=r"(a) : "l"(p));
    return a;
}
__device__ __forceinline__ void cp_async16(uint32_t dst, const void* src) {
    asm volatile("cp.async.cg.shared.global [%0], [%1], 16;"
                 :: "r"(dst), "l"(src) : "memory");
}
__device__ __forceinline__ void cp_commit() {
    asm volatile("cp.async.commit_group;" ::: "memory");
}
__device__ __forceinline__ void cp_wait0() {
    asm volatile("cp.async.wait_group 0;" ::: "memory");
}
__device__ __forceinline__ void mma_f16(float c[4], const uint32_t a[4],
                                        const uint32_t b[2]) {
    asm volatile(
        "mma.sync.aligned.m16n8k16.row.col.f32.f16.f16.f32 "
        "{%0,%1,%2,%3}, {%4,%5,%6,%7}, {%8,%9}, {%0,%1,%2,%3};"
        : "+f"(c[0]), "+f"(c[1]), "+f"(c[2]), "+f"(c[3])
        : "r"(a[0]), "r"(a[1]), "r"(a[2]), "r"(a[3]), "r"(b[0]), "r"(b[1]));
}
__device__ __forceinline__ void ldsm_x4(uint32_t r[4], uint32_t addr) {
    asm volatile("ldmatrix.sync.aligned.m8n8.x4.shared.b16 {%0,%1,%2,%3}, [%4];"
                 : "=r"(r[0]), "=r"(r[1]), "=r"(r[2]), "=r"(r[3]) : "r"(addr));
}
// fast accurate tanh: 1 - 2/(e^{2x}+1), ex2/rcp approx (err ~2^-21)
__device__ __forceinline__ float tanh_fast(float x) {
    const float e = __expf(2.f * x);
    return 1.f - __fdividef(2.f, e + 1.f);
}

// ---------------------------------------------------------------------------
// g_W1h[u][k] = half(W1[k][u])
// ---------------------------------------------------------------------------
__global__ void w1h_kernel(const float* __restrict__ W1) {
    __shared__ float sm[32][33];
    const int k0 = blockIdx.x * 32, u0 = blockIdx.y * 32;
    const int tx = threadIdx.x, ty = threadIdx.y;
#pragma unroll
    for (int j = 0; j < 4; ++j) {
        const int r = ty + j * 8;
        sm[r][tx] = W1[(size_t)(k0 + r) * UU + u0 + tx];
    }
    __syncthreads();
#pragma unroll
    for (int j = 0; j < 4; ++j) {
        const int r = ty + j * 8;
        g_W1h[(size_t)(u0 + r) * DD + k0 + tx] = __float2half_rn(sm[tx][r]);
    }
}

// ---------------------------------------------------------------------------
__global__ void hq_kernel(const float* __restrict__ query,
                          const float* __restrict__ W2,
                          const float* __restrict__ b1,
                          const float* __restrict__ b2) {
    __shared__ float q[DD];
    const int b = blockIdx.x;
    const int u = threadIdx.x;
    for (int i = threadIdx.x; i < DD; i += blockDim.x) q[i] = query[b * DD + i];
    __syncthreads();
    float acc = b1[u] + b2[u];
#pragma unroll 8
    for (int d = 0; d < DD; ++d) acc = fmaf(q[d], W2[d * UU + u], acc);
    g_hq[b * UU + u] = acc;
}

// ---------------------------------------------------------------------------
// scores: fp16 mma.m16n8k16, 128t x 256u x 512k per CTA, 512 thr (2M x 8N),
// double-buffered cp.async(B)/reg-prefetch(A), ldmatrix fragment loads.
// ---------------------------------------------------------------------------
__global__ __launch_bounds__(512, 1)
void scores_mma(const float* __restrict__ values,
                const float* __restrict__ Vv) {
    extern __shared__ char smc[];
    __half* As   = (__half*)smc;                 // 2 x [128][APH]
    __half* Bs   = (__half*)(smc + 20480);       // 2 x [256][BPH]
    float*  sred = (float*)(smc + 61440);        // [128]
    const uint32_t As_u32 = smem_u32(As);
    const uint32_t Bs_u32 = smem_u32(Bs);

    const int b     = blockIdx.y;
    const int tbase = blockIdx.x * 128;
    const int tid   = threadIdx.x;
    const int lane  = tid & 31;
    const int wid   = tid >> 5;
    const int wm    = wid & 1;            // M half (64 rows each)
    const int wn    = wid >> 1;           // N: 8 x 32 u
    const int g     = lane >> 2;
    const int tg    = lane & 3;

    // ldmatrix lane->address components
    const int lrow = lane & 15;           // row within 16-row tile
    const int lk8  = (lane & 16) >> 1;    // 0 or 8 halves (second k8 block)

    const float* vbase = values + ((size_t)b * TT + tbase) * DD;

    // staging coords
    const int at0 = tid >> 3;             // A rows at0, at0+64 ; col k4a*4 floats
    const int k4a = tid & 7;
    const int ub  = tid >> 1;             // B row u (0..255)
    const int hk  = (tid & 1) * 16;       // halves offset within 32-k row

    float acc[4][4][4];
#pragma unroll
    for (int i = 0; i < 4; ++i)
#pragma unroll
        for (int j = 0; j < 4; ++j)
#pragma unroll
            for (int c = 0; c < 4; ++c) acc[i][j][c] = 0.f;

    float4 pfA0, pfA1;

    // ---- prologue: stage chunk 0 ----
    {
        const __half* w1p = g_W1h + (size_t)ub * DD + hk;
        const uint32_t bdst = Bs_u32 + (ub * BPH + hk) * 2;
        cp_async16(bdst, w1p);
        cp_async16(bdst + 16, w1p + 8);
        cp_commit();
        pfA0 = *(const float4*)(vbase + (size_t)at0 * DD + k4a * 4);
        pfA1 = *(const float4*)(vbase + (size_t)(at0 + 64) * DD + k4a * 4);
        __half2 p0 = __floats2half2_rn(pfA0.x, pfA0.y);
        __half2 p1 = __floats2half2_rn(pfA0.z, pfA0.w);
        __half2 p2 = __floats2half2_rn(pfA1.x, pfA1.y);
        __half2 p3 = __floats2half2_rn(pfA1.z, pfA1.w);
        uint2 s0 = make_uint2(*(uint32_t*)&p0, *(uint32_t*)&p1);
        uint2 s1 = make_uint2(*(uint32_t*)&p2, *(uint32_t*)&p3);
        *(uint2*)(As + at0 * APH + k4a * 4) = s0;
        *(uint2*)(As + (at0 + 64) * APH + k4a * 4) = s1;
        cp_wait0();
    }
    __syncthreads();

    for (int c = 0; c < 16; ++c) {
        const int buf = c & 1;
        const int nxt = buf ^ 1;

        if (c < 15) {
            const int k0n = (c + 1) * 32;
            const __half* w1p = g_W1h + (size_t)ub * DD + k0n + hk;
            const uint32_t bdst = Bs_u32 + (nxt * 256 * BPH + ub * BPH + hk) * 2;
            cp_async16(bdst, w1p);
            cp_async16(bdst + 16, w1p + 8);
            cp_commit();
            pfA0 = *(const float4*)(vbase + (size_t)at0 * DD + k0n + k4a * 4);
            pfA1 = *(const float4*)(vbase + (size_t)(at0 + 64) * DD + k0n + k4a * 4);
        }

        // ---- compute chunk c (2 k16 steps), ldmatrix fragments ----
        const uint32_t Abase = As_u32 + buf * 128 * APH * 2;
        const uint32_t Bbase = Bs_u32 + buf * 256 * BPH * 2;
#pragma unroll
        for (int ks = 0; ks < 2; ++ks) {
            const int kk = ks * 16;
            uint32_t a[4][4];
#pragma unroll
            for (int mi = 0; mi < 4; ++mi) {
                const int row = wm * 64 + mi * 16 + lrow;
                ldsm_x4(a[mi], Abase + (row * APH + kk + lk8) * 2);
            }
            uint32_t bf[4][2];
#pragma unroll
            for (int j = 0; j < 2; ++j) {
                uint32_t r[4];
                const int u = wn * 32 + j * 16 + lrow;
                ldsm_x4(r, Bbase + (u * BPH + kk + lk8) * 2);
                bf[2 * j][0]     = r[0];
                bf[2 * j + 1][0] = r[1];
                bf[2 * j][1]     = r[2];
                bf[2 * j + 1][1] = r[3];
            }
#pragma unroll
            for (int mi = 0; mi < 4; ++mi)
#pragma unroll
                for (int nj = 0; nj < 4; ++nj)
                    mma_f16(acc[mi][nj], a[mi], bf[nj]);
        }

        if (c < 15) {
            __half* An = As + nxt * 128 * APH;
            __half2 p0 = __floats2half2_rn(pfA0.x, pfA0.y);
            __half2 p1 = __floats2half2_rn(pfA0.z, pfA0.w);
            __half2 p2 = __floats2half2_rn(pfA1.x, pfA1.y);
            __half2 p3 = __floats2half2_rn(pfA1.z, pfA1.w);
            uint2 s0 = make_uint2(*(uint32_t*)&p0, *(uint32_t*)&p1);
            uint2 s1 = make_uint2(*(uint32_t*)&p2, *(uint32_t*)&p3);
            *(uint2*)(An + at0 * APH + k4a * 4) = s0;
            *(uint2*)(An + (at0 + 64) * APH + k4a * 4) = s1;
            cp_wait0();
            __syncthreads();
        }
    }

    // ---- epilogue: fast tanh + dot with V, reduce over u ----
    float sp[4][2];
#pragma unroll
    for (int mi = 0; mi < 4; ++mi) { sp[mi][0] = 0.f; sp[mi][1] = 0.f; }

#pragma unroll
    for (int nj = 0; nj < 4; ++nj) {
        const int u0  = wn * 32 + nj * 8 + 2 * tg;
        const float h0 = g_hq[b * UU + u0];
        const float h1 = g_hq[b * UU + u0 + 1];
        const float v0 = Vv[u0];
        const float v1 = Vv[u0 + 1];
#pragma unroll
        for (int mi = 0; mi < 4; ++mi) {
            sp[mi][0] = fmaf(tanh_fast(acc[mi][nj][0] + h0), v0, sp[mi][0]);
            sp[mi][0] = fmaf(tanh_fast(acc[mi][nj][1] + h1), v1, sp[mi][0]);
            sp[mi][1] = fmaf(tanh_fast(acc[mi][nj][2] + h0), v0, sp[mi][1]);
            sp[mi][1] = fmaf(tanh_fast(acc[mi][nj][3] + h1), v1, sp[mi][1]);
        }
    }
#pragma unroll
    for (int off = 1; off <= 2; off <<= 1)
#pragma unroll
        for (int mi = 0; mi < 4; ++mi) {
            sp[mi][0] += __shfl_xor_sync(0xffffffffu, sp[mi][0], off);
            sp[mi][1] += __shfl_xor_sync(0xffffffffu, sp[mi][1], off);
        }

    if (tid < 128) sred[tid] = 0.f;
    __syncthreads();
    if (tg == 0) {
#pragma unroll
        for (int mi = 0; mi < 4; ++mi) {
            atomicAdd(&sred[wm * 64 + mi * 16 + g],     sp[mi][0]);
            atomicAdd(&sred[wm * 64 + mi * 16 + g + 8], sp[mi][1]);
        }
    }
    __syncthreads();
    if (tid < 128) g_scores[(size_t)b * TT + tbase + tid] = sred[tid];
}

// ---------------------------------------------------------------------------
// softmax over T per batch; 1024 threads
// ---------------------------------------------------------------------------
__global__ void softmax_kernel(float* __restrict__ wout) {
    __shared__ float red[32];
    __shared__ float bcast;
    const int b   = blockIdx.x;
    const int tid = threadIdx.x;
    float* s = g_scores + (size_t)b * TT;

    float m = -3.4e38f;
    for (int i = tid; i < TT; i += 1024) m = fmaxf(m, s[i]);
#pragma unroll
    for (int off = 16; off; off >>= 1)
        m = fmaxf(m, __shfl_xor_sync(0xffffffffu, m, off));
    if ((tid & 31) == 0) red[tid >> 5] = m;
    __syncthreads();
    if (tid == 0) {
        float mm = red[0];
        for (int i = 1; i < 32; ++i) mm = fmaxf(mm, red[i]);
        bcast = mm;
    }
    __syncthreads();
    m = bcast;

    float sum = 0.f;
    for (int i = tid; i < TT; i += 1024) {
        const float e = expf(s[i] - m);
        s[i] = e;
        sum += e;
    }
#pragma unroll
    for (int off = 16; off; off >>= 1)
        sum += __shfl_xor_sync(0xffffffffu, sum, off);
    if ((tid & 31) == 0) red[tid >> 5] = sum;
    __syncthreads();
    if (tid == 0) {
        float t = 0.f;
        for (int i = 0; i < 32; ++i) t += red[i];
        bcast = 1.f / t;
    }
    __syncthreads();
    const float inv = bcast;

    for (int i = tid; i < TT; i += 1024) {
        const float wv = s[i] * inv;
        s[i] = wv;
        if (wout) wout[(size_t)b * TT + i] = wv;
    }
}

// ---------------------------------------------------------------------------
// context[b][d] = sum_t weights[b][t] * values[b][t][d]
// ---------------------------------------------------------------------------
__global__ void zero_ctx_kernel(float* __restrict__ ctx) {
    ctx[blockIdx.x * 256 + threadIdx.x] = 0.f;
}

__global__ void ctx_kernel(const float* __restrict__ values,
                           float* __restrict__ ctx) {
    const int b  = blockIdx.y;
    const int d4 = threadIdx.x;                // 0..127
    const int tstart = blockIdx.x * (TT / 32);
    const float4* vb = (const float4*)(values + (size_t)b * TT * DD) + d4;
    const float*  w  = g_scores + (size_t)b * TT;

    float4 acc = make_float4(0.f, 0.f, 0.f, 0.f);
#pragma unroll 4
    for (int t = tstart; t < tstart + TT / 32; ++t) {
        const float wv = w[t];
        const float4 v = vb[(size_t)t * (DD / 4)];
        acc.x = fmaf(wv, v.x, acc.x);
        acc.y = fmaf(wv, v.y, acc.y);
        acc.z = fmaf(wv, v.z, acc.z);
        acc.w = fmaf(wv, v.w, acc.w);
    }
    float* o = ctx + b * DD + d4 * 4;
    atomicAdd(o + 0, acc.x);
    atomicAdd(o + 1, acc.y);
    atomicAdd(o + 2, acc.z);
    atomicAdd(o + 3, acc.w);
}

// ---------------------------------------------------------------------------
extern "C" void kernel_launch(void* const* d_in, const int* in_sizes, int n_in,
                              void* d_out, int out_size) {
    const float* values = (const float*)d_in[0];
    const float* query  = (const float*)d_in[1];
    const float* W1     = (const float*)d_in[2];
    const float* b1     = (const float*)d_in[3];
    const float* W2     = (const float*)d_in[4];
    const float* b2     = (const float*)d_in[5];
    const float* Vv     = (const float*)d_in[6];
    // d_in[7] = bV: constant logit shift, cancels exactly in softmax.

    float* out  = (float*)d_out;
    float* ctx  = nullptr;
    float* wout = nullptr;
    if (out_size >= BB * DD + BB * TT) {
        ctx  = out;
        wout = out + BB * DD;
    } else if (out_size == BB * TT) {
        wout = out;
    } else {
        ctx = out;
    }

    const int smem_bytes = 61440 + 128 * sizeof(float);
    cudaFuncSetAttribute(scores_mma, cudaFuncAttributeMaxDynamicSharedMemorySize,
                         smem_bytes);

    w1h_kernel<<<dim3(DD / 32, UU / 32), dim3(32, 8)>>>(W1);
    hq_kernel<<<BB, 256>>>(query, W2, b1, b2);
    scores_mma<<<dim3(TT / 128, BB), 512, smem_bytes>>>(values, Vv);
    softmax_kernel<<<BB, 1024>>>(wout);
    if (ctx) {
        zero_ctx_kernel<<<(BB * DD) / 256, 256>>>(ctx);
        ctx_kernel<<<dim3(32, BB), 128>>>(values, ctx);
    }
}